// round 8
// baseline (speedup 1.0000x reference)
#include <cuda_runtime.h>
#include <cuda_fp16.h>
#include <cstdint>
#include <math.h>

#define RB 8
#define NN 128
#define DD 512
#define HH 256
#define KK 64

// ---------------------------------------------------------------------------
// Scratch (__device__ globals; no allocation allowed)
// ---------------------------------------------------------------------------
__device__ float g_lacc[RB * NN * NN];
__device__ float g_probs[NN * NN];
__device__ int   g_topk[KK];
__device__ float g_pf[KK * DD];
__device__ uint4 g_wfragH[32 * 32 * 32];  // [kc][ntg][lane] = (bh0,bh1,bl0,bl1)

__device__ __forceinline__ uint32_t h2u(half2 h) {
    return *reinterpret_cast<uint32_t*>(&h);
}

__device__ __forceinline__ void mma_f16(float* c, const uint32_t* a, uint32_t b0, uint32_t b1) {
    asm volatile(
        "mma.sync.aligned.m16n8k16.row.col.f32.f16.f16.f32 "
        "{%0,%1,%2,%3}, {%4,%5,%6,%7}, {%8,%9}, {%0,%1,%2,%3};"
        : "+f"(c[0]), "+f"(c[1]), "+f"(c[2]), "+f"(c[3])
        : "r"(a[0]), "r"(a[1]), "r"(a[2]), "r"(a[3]), "r"(b0), "r"(b1));
}

#define CP_ASYNC16(dst_u32, src_ptr) \
    asm volatile("cp.async.cg.shared.global [%0], [%1], 16;" :: "r"(dst_u32), "l"(src_ptr))
#define CP_COMMIT() asm volatile("cp.async.commit_group;")
#define CP_WAIT0()  asm volatile("cp.async.wait_group 0;" ::: "memory")

// SMEM float offsets (per CTA; 52352 B)
#define SM_G    0        // [2][1024]
#define SM_O    2048     // [2][1024]
#define SM_B    4096     // [2][4096]
#define SM_OI   12288    // [2][16]
#define SM_RED  12320    // [256]
#define SM_W2   12576    // [256]
#define SM_B1   12832    // [256]
#define SM_TOT  13088

// ---------------------------------------------------------------------------
// K0: pack w1a (scaled x16) into fp16 hi/lo MMA B-fragment quads.
//     quad(kc,ntg,lane): n = ntg*8+(lane>>2); k = kc*16 + {2gc,2gc+1 | +8,+9}
// ---------------------------------------------------------------------------
__global__ void k0_pack(const float* __restrict__ w1a)
{
    int w = blockIdx.x * 256 + threadIdx.x;     // 32768
    int lane = w & 31, ntg = (w >> 5) & 31, kc = w >> 10;
    int n = ntg * 8 + (lane >> 2), gc = lane & 3, k0 = kc * 16;
    const float S = 16.f;
    float a0 = w1a[(k0 + 2 * gc) * HH + n] * S;
    float a1 = w1a[(k0 + 2 * gc + 1) * HH + n] * S;
    float a2 = w1a[(k0 + 2 * gc + 8) * HH + n] * S;
    float a3 = w1a[(k0 + 2 * gc + 9) * HH + n] * S;
    half2 h0 = __floats2half2_rn(a0, a1), h1 = __floats2half2_rn(a2, a3);
    half2 l0 = __floats2half2_rn(a0 - __low2float(h0), a1 - __high2float(h0));
    half2 l1 = __floats2half2_rn(a2 - __low2float(h1), a3 - __high2float(h1));
    g_wfragH[w] = make_uint4(h2u(h0), h2u(h1), h2u(l0), h2u(l1));
}

// ---------------------------------------------------------------------------
// K1: 3-pass fp16 warp-mma GEMM. One (i, r, j-half) per CTA: M=64, N=256, K=512.
//     256 threads (8 warps: 2 mw x 4 nw). 2 CTAs/SM to hide barrier/mem stalls.
// ---------------------------------------------------------------------------
__global__ __launch_bounds__(256, 2)
void k1_mma(const float* __restrict__ obj, const float* __restrict__ geo,
            const float* __restrict__ b1a, const float* __restrict__ w2a)
{
    extern __shared__ float sm[];
    float* Gb  = sm + SM_G;
    float* Ob  = sm + SM_O;
    float* Bq  = sm + SM_B;
    float* OiS = sm + SM_OI;
    float* red = sm + SM_RED;
    float* w2s = sm + SM_W2;
    float* b1s = sm + SM_B1;

    const int t    = threadIdx.x;
    const int lane = t & 31;
    const int wid  = t >> 5;          // 0..7
    const int mw   = wid & 1;
    const int nw   = wid >> 1;        // 0..3
    const int gr   = lane >> 2;
    const int gc   = lane & 3;
    const int mbase = mw * 32;

    const int bx = blockIdx.x;        // 0..2047
    const int i  = bx >> 4;
    const int r  = (bx >> 1) & 7;
    const int mh = bx & 1;

    const float* obj_r  = obj + (size_t)r * NN * DD;
    const float* obj_i  = obj_r + (size_t)i * DD;
    const float* geo_ri = geo + ((size_t)(r * NN + i) * NN) * DD;

    w2s[t] = w2a[t];
    b1s[t] = b1a[t];

    // copy-role constants: thread stages row crow (0..63) granule cgq of geo/obj
    const int crow = t >> 2;
    const int cgq  = t & 3;
    const int adst = crow * 16 + ((cgq ^ (crow & 3)) << 2);
    const float* gsrc0 = geo_ri + (size_t)(mh * 64 + crow) * DD + cgq * 4;
    const float* osrc0 = obj_r  + (size_t)(mh * 64 + crow) * DD + cgq * 4;
    const uint32_t sbase = (uint32_t)__cvta_generic_to_shared(sm);

    float c[2][8][4];
#pragma unroll
    for (int mt = 0; mt < 2; mt++)
#pragma unroll
        for (int nt = 0; nt < 8; nt++)
#pragma unroll
            for (int e = 0; e < 4; e++) c[mt][nt][e] = 0.f;

    // ---- prologue: stage 0 copies for chunk 0 ----
    {
        CP_ASYNC16(sbase + (SM_G + adst) * 4, gsrc0);
        CP_ASYNC16(sbase + (SM_O + adst) * 4, osrc0);
#pragma unroll
        for (int q = 0; q < 4; q++)
            CP_ASYNC16(sbase + (SM_B + (t + q * 256) * 4) * 4, g_wfragH + t + q * 256);
        if (t < 4) CP_ASYNC16(sbase + (SM_OI + t * 4) * 4, obj_i + t * 4);
        CP_COMMIT();
    }

    for (int kc = 0; kc < 32; kc++) {
        const int s = kc & 1;
        CP_WAIT0();
        __syncthreads();

        if (kc < 31) {
            const int s1 = s ^ 1;
            const int kf = (kc + 1) * 16;
            CP_ASYNC16(sbase + (SM_G + s1 * 1024 + adst) * 4, gsrc0 + kf);
            CP_ASYNC16(sbase + (SM_O + s1 * 1024 + adst) * 4, osrc0 + kf);
            const uint4* bsrc = g_wfragH + (size_t)(kc + 1) * 1024;
#pragma unroll
            for (int q = 0; q < 4; q++)
                CP_ASYNC16(sbase + (SM_B + s1 * 4096 + (t + q * 256) * 4) * 4, bsrc + t + q * 256);
            if (t < 4) CP_ASYNC16(sbase + (SM_OI + s1 * 16 + t * 4) * 4, obj_i + kf + t * 4);
            CP_COMMIT();
        }

        // ---- build A fragments (hi/lo) in registers ----
        const float* G  = Gb + s * 1024;
        const float* O  = Ob + s * 1024;
        const float* Oi = OiS + s * 16;
        float2 oiv[2];
        oiv[0] = *(const float2*)(Oi + 2 * gc);
        oiv[1] = *(const float2*)(Oi + 8 + 2 * gc);

        uint32_t ah[2][4], al[2][4];
#pragma unroll
        for (int mt = 0; mt < 2; mt++)
#pragma unroll
            for (int rh = 0; rh < 2; rh++) {
                const int rr = mbase + mt * 16 + rh * 8 + gr;   // 0..63
                const int rb = rr * 16, ra = rr & 3;
#pragma unroll
                for (int kp = 0; kp < 2; kp++) {
                    const int ad = rb + (((kp * 2 + (gc >> 1)) ^ ra) << 2) + 2 * (gc & 1);
                    float2 gx = *(const float2*)(G + ad);
                    float2 ox = *(const float2*)(O + ad);
                    float X0 = fmaf(oiv[kp].x, ox.x, gx.x);
                    float X1 = fmaf(oiv[kp].y, ox.y, gx.y);
                    half2 h = __floats2half2_rn(X0, X1);
                    float l0 = X0 - __low2float(h);
                    float l1 = X1 - __high2float(h);
                    ah[mt][rh + 2 * kp] = h2u(h);
                    al[mt][rh + 2 * kp] = h2u(__floats2half2_rn(l0, l1));
                }
            }

        // ---- MMAs: 8 nt x 2 mt x 3 passes ----
        const float* Bs = Bq + s * 4096;
#pragma unroll
        for (int nt = 0; nt < 8; nt++) {
            const uint4 bq = *(const uint4*)(Bs + ((nw * 8 + nt) * 32 + lane) * 4);
#pragma unroll
            for (int mt = 0; mt < 2; mt++) {
                mma_f16(c[mt][nt], ah[mt], bq.x, bq.y);
                mma_f16(c[mt][nt], ah[mt], bq.z, bq.w);
                mma_f16(c[mt][nt], al[mt], bq.x, bq.y);
            }
        }
    }

    // ---- epilogue: logit[j] = sum_h relu(C/16 + b1a) * w2a, reduce across nw ----
    float part[2][2] = {{0.f, 0.f}, {0.f, 0.f}};
#pragma unroll
    for (int mt = 0; mt < 2; mt++)
#pragma unroll
        for (int nt = 0; nt < 8; nt++)
#pragma unroll
            for (int rv = 0; rv < 2; rv++)
#pragma unroll
                for (int e = 0; e < 2; e++) {
                    int h = nw * 64 + nt * 8 + gc * 2 + e;
                    float v = c[mt][nt][rv * 2 + e] * 0.0625f + b1s[h];
                    part[mt][rv] += fmaxf(v, 0.f) * w2s[h];
                }
    __syncthreads();
#pragma unroll
    for (int mt = 0; mt < 2; mt++)
#pragma unroll
        for (int rv = 0; rv < 2; rv++) {
            float p = part[mt][rv];
            p += __shfl_xor_sync(0xffffffffu, p, 1);
            p += __shfl_xor_sync(0xffffffffu, p, 2);
            if (gc == 0)
                red[nw * 64 + mbase + mt * 16 + rv * 8 + gr] = p;
        }
    __syncthreads();
    if (t < 64)
        g_lacc[(r * NN + i) * NN + mh * 64 + t] =
            (red[t] + red[64 + t]) + (red[128 + t] + red[192 + t]);
}

// ---------------------------------------------------------------------------
// K2: mean over r + b2a -> out; probs = sigmoid*mask
// ---------------------------------------------------------------------------
__global__ void k2_finish(const float* __restrict__ mask,
                          const float* __restrict__ b2a,
                          float* __restrict__ out)
{
    int idx = blockIdx.x * 256 + threadIdx.x;
    float s = 0.f;
#pragma unroll
    for (int r = 0; r < RB; r++) s += g_lacc[r * (NN * NN) + idx];
    float v = s * 0.125f + b2a[0];
    out[idx] = v;
    g_probs[idx] = (1.f / (1.f + expf(-v))) * mask[idx];
}

// ---------------------------------------------------------------------------
// K3: top-64, single warp. Per-thread sorted top-8 cache over 512 elems,
//     512-bit taken mask, butterfly argmax, rescan on exhaustion.
// ---------------------------------------------------------------------------
__global__ void k3_topk(float* __restrict__ out)
{
    const int t = threadIdx.x;        // 32 threads
    const int base = t << 9;          // *512

    float v[8]; int ix[8];
    unsigned long long taken[8];
#pragma unroll
    for (int q = 0; q < 8; q++) { v[q] = -1e30f; ix[q] = 0x7fffffff; taken[q] = 0ull; }

    for (int u = 0; u < 512; u++) {
        float vv = g_probs[base + u];
        if (vv > v[7]) {
            int pos = 7;
            while (pos > 0 && vv > v[pos - 1]) pos--;
            for (int q = 7; q > pos; q--) { v[q] = v[q - 1]; ix[q] = ix[q - 1]; }
            v[pos] = vv; ix[pos] = base + u;
        }
    }
    int cnt = 8;

    for (int it = 0; it < KK; it++) {
        float bv = v[0]; int bi = ix[0];
#pragma unroll
        for (int off = 16; off; off >>= 1) {
            float ov = __shfl_xor_sync(0xffffffffu, bv, off);
            int   oi = __shfl_xor_sync(0xffffffffu, bi, off);
            if (ov > bv || (ov == bv && oi < bi)) { bv = ov; bi = oi; }
        }
        if (t == 0) {
            g_topk[it] = bi;
            out[NN * NN + KK * KK + it] = (float)bi;
        }
        if ((bi >> 9) == t) {
            int loc = bi & 511;
            taken[loc >> 6] |= 1ull << (loc & 63);
            for (int q = 0; q < 7; q++) { v[q] = v[q + 1]; ix[q] = ix[q + 1]; }
            v[7] = -1e30f; ix[7] = 0x7fffffff;
            if (--cnt == 0) {
#pragma unroll
                for (int q = 0; q < 8; q++) { v[q] = -1e30f; ix[q] = 0x7fffffff; }
                for (int u = 0; u < 512; u++) {
                    if ((taken[u >> 6] >> (u & 63)) & 1ull) continue;
                    float vv = g_probs[base + u];
                    if (vv > v[7]) {
                        int pos = 7;
                        while (pos > 0 && vv > v[pos - 1]) pos--;
                        for (int q = 7; q > pos; q--) { v[q] = v[q - 1]; ix[q] = ix[q - 1]; }
                        v[pos] = vv; ix[pos] = base + u;
                    }
                }
                cnt = 8;
            }
        }
        __syncwarp();
    }
}

// ---------------------------------------------------------------------------
// K4: gather averaged pair features at top-k pairs
// ---------------------------------------------------------------------------
__global__ void k4_pf(const float* __restrict__ obj, const float* __restrict__ geo)
{
    int p = blockIdx.x;
    int t = threadIdx.x;
    int ind = g_topk[p];
    int i = ind >> 7;
    int j = ind & 127;
    int d = t * 4;

    float4 s = make_float4(0.f, 0.f, 0.f, 0.f);
#pragma unroll
    for (int r = 0; r < RB; r++) {
        float4 oi = *(const float4*)(obj + (size_t)(r * NN + i) * DD + d);
        float4 oj = *(const float4*)(obj + (size_t)(r * NN + j) * DD + d);
        float4 g  = *(const float4*)(geo + (size_t)((r * NN + i) * NN + j) * DD + d);
        s.x += fmaf(oi.x, oj.x, g.x);
        s.y += fmaf(oi.y, oj.y, g.y);
        s.z += fmaf(oi.z, oj.z, g.z);
        s.w += fmaf(oi.w, oj.w, g.w);
    }
    s.x *= 0.125f; s.y *= 0.125f; s.z *= 0.125f; s.w *= 0.125f;
    *(float4*)(g_pf + p * DD + d) = s;
}

// ---------------------------------------------------------------------------
// K5: p2p scorer (fp32, small)
// ---------------------------------------------------------------------------
__global__ __launch_bounds__(256, 2)
void k5_p2p(const float* __restrict__ w1b, const float* __restrict__ b1b,
            const float* __restrict__ w2b, const float* __restrict__ b2b,
            float* __restrict__ out)
{
    __shared__ float As2[16][17];
    __shared__ float Bs2[16][256];

    int t = threadIdx.x;
    int b = blockIdx.x;
    int row0   = b * 16;
    int i2     = row0 >> 6;
    int j2base = row0 & 63;
    int rowl = t >> 4;
    int hg   = t & 15;

    const float* pfi = g_pf + i2 * DD;
    float acc[16];
#pragma unroll
    for (int hh = 0; hh < 16; hh++) acc[hh] = 0.f;

    for (int d0 = 0; d0 < DD; d0 += 16) {
        {
            int rl = t >> 4, k = t & 15;
            As2[k][rl] = pfi[d0 + k] * g_pf[(j2base + rl) * DD + d0 + k];
        }
#pragma unroll
        for (int l = 0; l < 4; l++) {
            int q  = t + l * 256;
            int k  = q >> 6;
            int h4 = (q & 63) << 2;
            *(float4*)&Bs2[k][h4] = *(const float4*)(w1b + (d0 + k) * HH + h4);
        }
        __syncthreads();
#pragma unroll 4
        for (int k = 0; k < 16; k++) {
            float a = As2[k][rowl];
            float bv[16];
            *(float4*)&bv[0]  = *(const float4*)&Bs2[k][hg * 16];
            *(float4*)&bv[4]  = *(const float4*)&Bs2[k][hg * 16 + 4];
            *(float4*)&bv[8]  = *(const float4*)&Bs2[k][hg * 16 + 8];
            *(float4*)&bv[12] = *(const float4*)&Bs2[k][hg * 16 + 12];
#pragma unroll
            for (int hh = 0; hh < 16; hh++)
                acc[hh] = fmaf(a, bv[hh], acc[hh]);
        }
        __syncthreads();
    }

    float p = 0.f;
#pragma unroll
    for (int hh = 0; hh < 16; hh++) {
        int h = hg * 16 + hh;
        p += fmaxf(acc[hh] + b1b[h], 0.f) * w2b[h];
    }
#pragma unroll
    for (int off = 8; off; off >>= 1)
        p += __shfl_xor_sync(0xffffffffu, p, off);
    if (hg == 0)
        out[NN * NN + row0 + rowl] = p + b2b[0];
}

// ---------------------------------------------------------------------------
extern "C" void kernel_launch(void* const* d_in, const int* in_sizes, int n_in,
                              void* d_out, int out_size)
{
    const float* obj  = (const float*)d_in[0];
    const float* geo  = (const float*)d_in[1];
    const float* mask = (const float*)d_in[2];
    const float* w1a  = (const float*)d_in[3];
    const float* b1a  = (const float*)d_in[4];
    const float* w2a  = (const float*)d_in[5];
    const float* b2a  = (const float*)d_in[6];
    const float* w1b  = (const float*)d_in[7];
    const float* b1b  = (const float*)d_in[8];
    const float* w2b  = (const float*)d_in[9];
    const float* b2b  = (const float*)d_in[10];
    float* out = (float*)d_out;

    const int smem_k1 = SM_TOT * 4;   // 52352 B
    cudaFuncSetAttribute(k1_mma, cudaFuncAttributeMaxDynamicSharedMemorySize, smem_k1);

    k0_pack<<<128, 256>>>(w1a);
    k1_mma<<<2048, 256, smem_k1>>>(obj, geo, b1a, w2a);
    k2_finish<<<64, 256>>>(mask, b2a, out);
    k3_topk<<<1, 32>>>(out);
    k4_pf<<<KK, 128>>>(obj, geo);
    k5_p2p<<<256, 256>>>(w1b, b1b, w2b, b2b, out);
}

// round 14
// speedup vs baseline: 1.1838x; 1.1838x over previous
#include <cuda_runtime.h>
#include <cuda_fp16.h>
#include <cstdint>
#include <math.h>

#define RB 8
#define NN 128
#define DD 512
#define HH 256
#define KK 64

// ---------------------------------------------------------------------------
// Scratch (__device__ globals; no allocation allowed)
// ---------------------------------------------------------------------------
__device__ float g_lacc[RB * NN * NN];
__device__ float g_probs[NN * NN];
__device__ int   g_topk[KK];
__device__ float g_pf[KK * DD];
__device__ uint4 g_wfragH[32 * 32 * 32];  // [kc][ntg][lane] = (bh0,bh1,bl0,bl1)

__device__ __forceinline__ uint32_t h2u(half2 h) {
    return *reinterpret_cast<uint32_t*>(&h);
}

__device__ __forceinline__ void mma_f16(float* c, const uint32_t* a, uint32_t b0, uint32_t b1) {
    asm volatile(
        "mma.sync.aligned.m16n8k16.row.col.f32.f16.f16.f32 "
        "{%0,%1,%2,%3}, {%4,%5,%6,%7}, {%8,%9}, {%0,%1,%2,%3};"
        : "+f"(c[0]), "+f"(c[1]), "+f"(c[2]), "+f"(c[3])
        : "r"(a[0]), "r"(a[1]), "r"(a[2]), "r"(a[3]), "r"(b0), "r"(b1));
}

#define CP_ASYNC16(dst_u32, src_ptr) \
    asm volatile("cp.async.cg.shared.global [%0], [%1], 16;" :: "r"(dst_u32), "l"(src_ptr))
#define CP_COMMIT() asm volatile("cp.async.commit_group;")
#define CP_WAIT0()  asm volatile("cp.async.wait_group 0;" ::: "memory")

// SMEM float offsets (per CTA; 52352 B)
#define SM_G    0        // [2][1024]
#define SM_O    2048     // [2][1024]
#define SM_B    4096     // [2][4096]
#define SM_OI   12288    // [2][16]
#define SM_RED  12320    // [256]
#define SM_W2   12576    // [256]
#define SM_B1   12832    // [256]
#define SM_TOT  13088

// ---------------------------------------------------------------------------
// K0: pack w1a (scaled x16) into fp16 hi/lo MMA B-fragment quads.
// ---------------------------------------------------------------------------
__global__ void k0_pack(const float* __restrict__ w1a)
{
    int w = blockIdx.x * 256 + threadIdx.x;     // 32768
    int lane = w & 31, ntg = (w >> 5) & 31, kc = w >> 10;
    int n = ntg * 8 + (lane >> 2), gc = lane & 3, k0 = kc * 16;
    const float S = 16.f;
    float a0 = w1a[(k0 + 2 * gc) * HH + n] * S;
    float a1 = w1a[(k0 + 2 * gc + 1) * HH + n] * S;
    float a2 = w1a[(k0 + 2 * gc + 8) * HH + n] * S;
    float a3 = w1a[(k0 + 2 * gc + 9) * HH + n] * S;
    half2 h0 = __floats2half2_rn(a0, a1), h1 = __floats2half2_rn(a2, a3);
    half2 l0 = __floats2half2_rn(a0 - __low2float(h0), a1 - __high2float(h0));
    half2 l1 = __floats2half2_rn(a2 - __low2float(h1), a3 - __high2float(h1));
    g_wfragH[w] = make_uint4(h2u(h0), h2u(h1), h2u(l0), h2u(l1));
}

// ---------------------------------------------------------------------------
// K1: 3-pass fp16 warp-mma GEMM. One (i, r, j-half) per CTA: M=64, N=256, K=512.
//     256 threads (8 warps: 2 mw x 4 nw). 2 CTAs/SM hides barrier/mem stalls.
// ---------------------------------------------------------------------------
__global__ __launch_bounds__(256, 2)
void k1_mma(const float* __restrict__ obj, const float* __restrict__ geo,
            const float* __restrict__ b1a, const float* __restrict__ w2a)
{
    extern __shared__ float sm[];
    float* Gb  = sm + SM_G;
    float* Ob  = sm + SM_O;
    float* Bq  = sm + SM_B;
    float* OiS = sm + SM_OI;
    float* red = sm + SM_RED;
    float* w2s = sm + SM_W2;
    float* b1s = sm + SM_B1;

    const int t    = threadIdx.x;
    const int lane = t & 31;
    const int wid  = t >> 5;          // 0..7
    const int mw   = wid & 1;
    const int nw   = wid >> 1;        // 0..3
    const int gr   = lane >> 2;
    const int gc   = lane & 3;
    const int mbase = mw * 32;

    const int bx = blockIdx.x;        // 0..2047
    const int i  = bx >> 4;
    const int r  = (bx >> 1) & 7;
    const int mh = bx & 1;

    const float* obj_r  = obj + (size_t)r * NN * DD;
    const float* obj_i  = obj_r + (size_t)i * DD;
    const float* geo_ri = geo + ((size_t)(r * NN + i) * NN) * DD;

    w2s[t] = w2a[t];
    b1s[t] = b1a[t];

    const int crow = t >> 2;
    const int cgq  = t & 3;
    const int adst = crow * 16 + ((cgq ^ (crow & 3)) << 2);
    const float* gsrc0 = geo_ri + (size_t)(mh * 64 + crow) * DD + cgq * 4;
    const float* osrc0 = obj_r  + (size_t)(mh * 64 + crow) * DD + cgq * 4;
    const uint32_t sbase = (uint32_t)__cvta_generic_to_shared(sm);

    float c[2][8][4];
#pragma unroll
    for (int mt = 0; mt < 2; mt++)
#pragma unroll
        for (int nt = 0; nt < 8; nt++)
#pragma unroll
            for (int e = 0; e < 4; e++) c[mt][nt][e] = 0.f;

    // ---- prologue: stage 0 copies for chunk 0 ----
    {
        CP_ASYNC16(sbase + (SM_G + adst) * 4, gsrc0);
        CP_ASYNC16(sbase + (SM_O + adst) * 4, osrc0);
#pragma unroll
        for (int q = 0; q < 4; q++)
            CP_ASYNC16(sbase + (SM_B + (t + q * 256) * 4) * 4, g_wfragH + t + q * 256);
        if (t < 4) CP_ASYNC16(sbase + (SM_OI + t * 4) * 4, obj_i + t * 4);
        CP_COMMIT();
    }

    for (int kc = 0; kc < 32; kc++) {
        const int s = kc & 1;
        CP_WAIT0();
        __syncthreads();

        if (kc < 31) {
            const int s1 = s ^ 1;
            const int kf = (kc + 1) * 16;
            CP_ASYNC16(sbase + (SM_G + s1 * 1024 + adst) * 4, gsrc0 + kf);
            CP_ASYNC16(sbase + (SM_O + s1 * 1024 + adst) * 4, osrc0 + kf);
            const uint4* bsrc = g_wfragH + (size_t)(kc + 1) * 1024;
#pragma unroll
            for (int q = 0; q < 4; q++)
                CP_ASYNC16(sbase + (SM_B + s1 * 4096 + (t + q * 256) * 4) * 4, bsrc + t + q * 256);
            if (t < 4) CP_ASYNC16(sbase + (SM_OI + s1 * 16 + t * 4) * 4, obj_i + kf + t * 4);
            CP_COMMIT();
        }

        // ---- build A fragments (hi/lo) in registers ----
        const float* G  = Gb + s * 1024;
        const float* O  = Ob + s * 1024;
        const float* Oi = OiS + s * 16;
        float2 oiv[2];
        oiv[0] = *(const float2*)(Oi + 2 * gc);
        oiv[1] = *(const float2*)(Oi + 8 + 2 * gc);

        uint32_t ah[2][4], al[2][4];
#pragma unroll
        for (int mt = 0; mt < 2; mt++)
#pragma unroll
            for (int rh = 0; rh < 2; rh++) {
                const int rr = mbase + mt * 16 + rh * 8 + gr;   // 0..63
                const int rb = rr * 16, ra = rr & 3;
#pragma unroll
                for (int kp = 0; kp < 2; kp++) {
                    const int ad = rb + (((kp * 2 + (gc >> 1)) ^ ra) << 2) + 2 * (gc & 1);
                    float2 gx = *(const float2*)(G + ad);
                    float2 ox = *(const float2*)(O + ad);
                    float X0 = fmaf(oiv[kp].x, ox.x, gx.x);
                    float X1 = fmaf(oiv[kp].y, ox.y, gx.y);
                    half2 h = __floats2half2_rn(X0, X1);
                    float l0 = X0 - __low2float(h);
                    float l1 = X1 - __high2float(h);
                    ah[mt][rh + 2 * kp] = h2u(h);
                    al[mt][rh + 2 * kp] = h2u(__floats2half2_rn(l0, l1));
                }
            }

        // ---- MMAs: 8 nt x 2 mt x 3 passes ----
        const float* Bs = Bq + s * 4096;
#pragma unroll
        for (int nt = 0; nt < 8; nt++) {
            const uint4 bq = *(const uint4*)(Bs + ((nw * 8 + nt) * 32 + lane) * 4);
#pragma unroll
            for (int mt = 0; mt < 2; mt++) {
                mma_f16(c[mt][nt], ah[mt], bq.x, bq.y);
                mma_f16(c[mt][nt], ah[mt], bq.z, bq.w);
                mma_f16(c[mt][nt], al[mt], bq.x, bq.y);
            }
        }
    }

    // ---- epilogue ----
    float part[2][2] = {{0.f, 0.f}, {0.f, 0.f}};
#pragma unroll
    for (int mt = 0; mt < 2; mt++)
#pragma unroll
        for (int nt = 0; nt < 8; nt++)
#pragma unroll
            for (int rv = 0; rv < 2; rv++)
#pragma unroll
                for (int e = 0; e < 2; e++) {
                    int h = nw * 64 + nt * 8 + gc * 2 + e;
                    float v = c[mt][nt][rv * 2 + e] * 0.0625f + b1s[h];
                    part[mt][rv] += fmaxf(v, 0.f) * w2s[h];
                }
    __syncthreads();
#pragma unroll
    for (int mt = 0; mt < 2; mt++)
#pragma unroll
        for (int rv = 0; rv < 2; rv++) {
            float p = part[mt][rv];
            p += __shfl_xor_sync(0xffffffffu, p, 1);
            p += __shfl_xor_sync(0xffffffffu, p, 2);
            if (gc == 0)
                red[nw * 64 + mbase + mt * 16 + rv * 8 + gr] = p;
        }
    __syncthreads();
    if (t < 64)
        g_lacc[(r * NN + i) * NN + mh * 64 + t] =
            (red[t] + red[64 + t]) + (red[128 + t] + red[192 + t]);
}

// ---------------------------------------------------------------------------
// K2: mean over r + b2a -> out; probs = sigmoid*mask
// ---------------------------------------------------------------------------
__global__ void k2_finish(const float* __restrict__ mask,
                          const float* __restrict__ b2a,
                          float* __restrict__ out)
{
    int idx = blockIdx.x * 256 + threadIdx.x;
    float s = 0.f;
#pragma unroll
    for (int r = 0; r < RB; r++) s += g_lacc[r * (NN * NN) + idx];
    float v = s * 0.125f + b2a[0];
    out[idx] = v;
    g_probs[idx] = (1.f / (1.f + expf(-v))) * mask[idx];
}

// ---------------------------------------------------------------------------
// K3: top-64, 256 threads x 64 elems, per-thread sorted top-4 register cache.
// ---------------------------------------------------------------------------
__global__ void k3_topk(float* __restrict__ out)
{
    __shared__ float wv[8];
    __shared__ int   wi[8];
    __shared__ int   bw_i;
    const int t = threadIdx.x;
    const int base = t * 64;

    float v0 = -1e30f, v1 = -1e30f, v2 = -1e30f, v3 = -1e30f;
    int   i0 = 0x7fffffff, i1 = 0x7fffffff, i2 = 0x7fffffff, i3 = 0x7fffffff;
#pragma unroll 4
    for (int u = 0; u < 64; u++) {
        float v = g_probs[base + u];
        int ix = base + u;
        if (v > v3) {
            if (v > v2) {
                v3 = v2; i3 = i2;
                if (v > v1) {
                    v2 = v1; i2 = i1;
                    if (v > v0) { v1 = v0; i1 = i0; v0 = v; i0 = ix; }
                    else        { v1 = v;  i1 = ix; }
                } else { v2 = v; i2 = ix; }
            } else { v3 = v; i3 = ix; }
        }
    }
    int cnt = 4;
    unsigned long long taken = 0ull;

    for (int it = 0; it < KK; it++) {
        float v = v0; int ix = i0;
#pragma unroll
        for (int off = 16; off; off >>= 1) {
            float ov = __shfl_down_sync(0xffffffffu, v, off);
            int   oi = __shfl_down_sync(0xffffffffu, ix, off);
            if (ov > v || (ov == v && oi < ix)) { v = ov; ix = oi; }
        }
        if ((t & 31) == 0) { wv[t >> 5] = v; wi[t >> 5] = ix; }
        __syncthreads();
        if (t < 32) {
            v  = (t < 8) ? wv[t] : -1e30f;
            ix = (t < 8) ? wi[t] : 0x7fffffff;
#pragma unroll
            for (int off = 4; off; off >>= 1) {
                float ov = __shfl_down_sync(0xffffffffu, v, off);
                int   oi = __shfl_down_sync(0xffffffffu, ix, off);
                if (ov > v || (ov == v && oi < ix)) { v = ov; ix = oi; }
            }
            if (t == 0) {
                bw_i = ix;
                g_topk[it] = ix;
                out[NN * NN + KK * KK + it] = (float)ix;
            }
        }
        __syncthreads();
        const int win = bw_i;
        if ((win >> 6) == t) {
            taken |= 1ull << (win & 63);
            v0 = v1; i0 = i1; v1 = v2; i1 = i2; v2 = v3; i2 = i3;
            v3 = -1e30f; i3 = 0x7fffffff;
            if (--cnt == 0) {
                v0 = v1 = v2 = v3 = -1e30f;
                i0 = i1 = i2 = i3 = 0x7fffffff;
                for (int u = 0; u < 64; u++) {
                    if ((taken >> u) & 1ull) continue;
                    float vv = g_probs[base + u];
                    int iu = base + u;
                    if (vv > v3) {
                        if (vv > v2) {
                            v3 = v2; i3 = i2;
                            if (vv > v1) {
                                v2 = v1; i2 = i1;
                                if (vv > v0) { v1 = v0; i1 = i0; v0 = vv; i0 = iu; }
                                else          { v1 = vv; i1 = iu; }
                            } else { v2 = vv; i2 = iu; }
                        } else { v3 = vv; i3 = iu; }
                    }
                }
                cnt = 4;
            }
        }
        __syncthreads();
    }
}

// ---------------------------------------------------------------------------
// K4: gather averaged pair features at top-k pairs
// ---------------------------------------------------------------------------
__global__ void k4_pf(const float* __restrict__ obj, const float* __restrict__ geo)
{
    int p = blockIdx.x;
    int t = threadIdx.x;
    int ind = g_topk[p];
    int i = ind >> 7;
    int j = ind & 127;
    int d = t * 4;

    float4 s = make_float4(0.f, 0.f, 0.f, 0.f);
#pragma unroll
    for (int r = 0; r < RB; r++) {
        float4 oi = *(const float4*)(obj + (size_t)(r * NN + i) * DD + d);
        float4 oj = *(const float4*)(obj + (size_t)(r * NN + j) * DD + d);
        float4 g  = *(const float4*)(geo + (size_t)((r * NN + i) * NN + j) * DD + d);
        s.x += fmaf(oi.x, oj.x, g.x);
        s.y += fmaf(oi.y, oj.y, g.y);
        s.z += fmaf(oi.z, oj.z, g.z);
        s.w += fmaf(oi.w, oj.w, g.w);
    }
    s.x *= 0.125f; s.y *= 0.125f; s.z *= 0.125f; s.w *= 0.125f;
    *(float4*)(g_pf + p * DD + d) = s;
}

// ---------------------------------------------------------------------------
// K5: p2p scorer (fp32, small)
// ---------------------------------------------------------------------------
__global__ __launch_bounds__(256, 2)
void k5_p2p(const float* __restrict__ w1b, const float* __restrict__ b1b,
            const float* __restrict__ w2b, const float* __restrict__ b2b,
            float* __restrict__ out)
{
    __shared__ float As2[16][17];
    __shared__ float Bs2[16][256];

    int t = threadIdx.x;
    int b = blockIdx.x;
    int row0   = b * 16;
    int i2     = row0 >> 6;
    int j2base = row0 & 63;
    int rowl = t >> 4;
    int hg   = t & 15;

    const float* pfi = g_pf + i2 * DD;
    float acc[16];
#pragma unroll
    for (int hh = 0; hh < 16; hh++) acc[hh] = 0.f;

    for (int d0 = 0; d0 < DD; d0 += 16) {
        {
            int rl = t >> 4, k = t & 15;
            As2[k][rl] = pfi[d0 + k] * g_pf[(j2base + rl) * DD + d0 + k];
        }
#pragma unroll
        for (int l = 0; l < 4; l++) {
            int q  = t + l * 256;
            int k  = q >> 6;
            int h4 = (q & 63) << 2;
            *(float4*)&Bs2[k][h4] = *(const float4*)(w1b + (d0 + k) * HH + h4);
        }
        __syncthreads();
#pragma unroll 4
        for (int k = 0; k < 16; k++) {
            float a = As2[k][rowl];
            float bv[16];
            *(float4*)&bv[0]  = *(const float4*)&Bs2[k][hg * 16];
            *(float4*)&bv[4]  = *(const float4*)&Bs2[k][hg * 16 + 4];
            *(float4*)&bv[8]  = *(const float4*)&Bs2[k][hg * 16 + 8];
            *(float4*)&bv[12] = *(const float4*)&Bs2[k][hg * 16 + 12];
#pragma unroll
            for (int hh = 0; hh < 16; hh++)
                acc[hh] = fmaf(a, bv[hh], acc[hh]);
        }
        __syncthreads();
    }

    float p = 0.f;
#pragma unroll
    for (int hh = 0; hh < 16; hh++) {
        int h = hg * 16 + hh;
        p += fmaxf(acc[hh] + b1b[h], 0.f) * w2b[h];
    }
#pragma unroll
    for (int off = 8; off; off >>= 1)
        p += __shfl_xor_sync(0xffffffffu, p, off);
    if (hg == 0)
        out[NN * NN + row0 + rowl] = p + b2b[0];
}

// ---------------------------------------------------------------------------
extern "C" void kernel_launch(void* const* d_in, const int* in_sizes, int n_in,
                              void* d_out, int out_size)
{
    const float* obj  = (const float*)d_in[0];
    const float* geo  = (const float*)d_in[1];
    const float* mask = (const float*)d_in[2];
    const float* w1a  = (const float*)d_in[3];
    const float* b1a  = (const float*)d_in[4];
    const float* w2a  = (const float*)d_in[5];
    const float* b2a  = (const float*)d_in[6];
    const float* w1b  = (const float*)d_in[7];
    const float* b1b  = (const float*)d_in[8];
    const float* w2b  = (const float*)d_in[9];
    const float* b2b  = (const float*)d_in[10];
    float* out = (float*)d_out;

    const int smem_k1 = SM_TOT * 4;   // 52352 B
    cudaFuncSetAttribute(k1_mma, cudaFuncAttributeMaxDynamicSharedMemorySize, smem_k1);

    k0_pack<<<128, 256>>>(w1a);
    k1_mma<<<2048, 256, smem_k1>>>(obj, geo, b1a, w2a);
    k2_finish<<<64, 256>>>(mask, b2a, out);
    k3_topk<<<1, 256>>>(out);
    k4_pf<<<KK, 128>>>(obj, geo);
    k5_p2p<<<256, 256>>>(w1b, b1b, w2b, b2b, out);
}